// round 6
// baseline (speedup 1.0000x reference)
#include <cuda_runtime.h>
#include <math.h>

// Kalman filter one-step-ahead predictions. B=512, T=256, S=32, M=4.
// TWO batches per warp (256 blocks x 32 threads): both filters share every
// F/H/Q shared-memory read (halves the dominant broadcast-LDS traffic) and
// their independent serial chains (Cholesky/solve) interleave for ILP.
// Register-resident symmetric P per batch (lane j holds column j == row j).
// Packed fma.rn.f32x2 GEMMs. rsqrt-form 4x4 Cholesky.

#define Bn 512
#define Tn 256
#define Sn 32
#define Mn 4
#define XLD 34  // sX row stride (floats): even (8B align) and degree-2 banks

using u64 = unsigned long long;

__device__ __forceinline__ u64 pack2(float lo, float hi) {
    u64 r; asm("mov.b64 %0,{%1,%2};" : "=l"(r) : "f"(lo), "f"(hi)); return r;
}
__device__ __forceinline__ void unpack2(u64 v, float& lo, float& hi) {
    asm("mov.b64 {%0,%1},%2;" : "=f"(lo), "=f"(hi) : "l"(v));
}
__device__ __forceinline__ u64 ffma2(u64 a, u64 b, u64 c) {
    u64 d; asm("fma.rn.f32x2 %0,%1,%2,%3;" : "=l"(d) : "l"(a), "l"(b), "l"(c)); return d;
}

__global__ __launch_bounds__(32) void kalman_kernel(
    const float* __restrict__ obs,       // [B,T,M]
    const float* __restrict__ Fm,        // [S,S]
    const float* __restrict__ Qm,        // [S,S]
    const float* __restrict__ Hm,        // [M,S]
    const float* __restrict__ Rm,        // [M,M]
    const float* __restrict__ init_mean, // [B,S]
    const float* __restrict__ init_cov,  // [B,S,S]
    float* __restrict__ out)
{
    const int bA   = blockIdx.x * 2;
    const int bB   = bA + 1;
    const int lane = threadIdx.x;

    // ---- constants (shared by both batches) ----
    __shared__ __align__(16) u64 sFTp[Sn * 18];  // fv[l*36+i] = F[i][l]
    __shared__ __align__(16) u64 sQp [Sn * 18];  // qv[j*36+i] = Q[i][j]
    __shared__ __align__(16) u64 sHTp[Sn * 2];   // hv[l*4+q]  = H[q][l]
    __shared__ __align__(16) u64 sHR [4 * 17];   // hr[q*34+l] = H[q][l]
    __shared__ __align__(16) u64 sFR [Sn * 17];  // fr[j*34+l] = F[j][l]
    __shared__ float sR16[16];
    // ---- per-batch scratch ----
    __shared__ __align__(16) u64   sPHT[2][4 * 17];   // pht[r*34+l]=(PH^T)[l][r]
    __shared__ __align__(16) float sX  [2][Sn * XLD];
    __shared__ __align__(16) float sZ  [2][Sn * 4];
    __shared__ __align__(16) u64   sMu [2][16];

    {
        float* fv  = (float*)sFTp;
        float* qv  = (float*)sQp;
        float* frf = (float*)sFR;
        for (int idx = lane; idx < Sn * Sn; idx += 32) {
            int i = idx >> 5, l = idx & 31;
            float f = Fm[idx];
            fv [l * 36 + i] = f;
            frf[i * 34 + l] = f;
            qv [l * 36 + i] = Qm[idx];
        }
        float* hv  = (float*)sHTp;
        float* hrf = (float*)sHR;
        for (int idx = lane; idx < Mn * Sn; idx += 32) {
            int q = idx >> 5, l = idx & 31;
            float h = Hm[idx];
            hv [l * 4 + q]  = h;
            hrf[q * 34 + l] = h;
        }
        if (lane < 16) sR16[lane] = Rm[lane];
    }

    // per-lane state for both batches
    float pA[Sn], pB[Sn];
#pragma unroll
    for (int i = 0; i < Sn; ++i) {
        pA[i] = init_cov[(size_t)bA * (Sn * Sn) + i * Sn + lane];
        pB[i] = init_cov[(size_t)bB * (Sn * Sn) + i * Sn + lane];
    }
    float mA = init_mean[bA * Sn + lane];
    float mB = init_mean[bB * Sn + lane];
    float Hl0 = Hm[0 * Sn + lane], Hl1 = Hm[1 * Sn + lane];
    float Hl2 = Hm[2 * Sn + lane], Hl3 = Hm[3 * Sn + lane];
    __syncwarp();

    const float* ybA = obs + (size_t)bA * (Tn * Mn);
    const float* ybB = obs + (size_t)bB * (Tn * Mn);
    float* out_means = out;                               // [T,B,M]
    float* out_covs  = out + (size_t)Tn * Bn * Mn;        // [T,B,M,M]

    float4 ynA = *(const float4*)ybA;
    float4 ynB = *(const float4*)ybB;
    float* phtA = (float*)sPHT[0];
    float* phtB = (float*)sPHT[1];
    float* muA  = (float*)sMu[0];
    float* muB  = (float*)sMu[1];

#pragma unroll 1
    for (int t = 0; t < Tn; ++t) {
        float4 yvA = ynA, yvB = ynB;
        int tnext = (t + 1 < Tn) ? (t + 1) : (Tn - 1);
        ynA = *(const float4*)(ybA + 4 * tnext);
        ynB = *(const float4*)(ybB + 4 * tnext);

        // ---- measurement means (8 butterfly chains, interleaved ILP)
        float cA0 = Hl0 * mA, cA1 = Hl1 * mA, cA2 = Hl2 * mA, cA3 = Hl3 * mA;
        float cB0 = Hl0 * mB, cB1 = Hl1 * mB, cB2 = Hl2 * mB, cB3 = Hl3 * mB;
#pragma unroll
        for (int s = 16; s >= 1; s >>= 1) {
            cA0 += __shfl_xor_sync(0xffffffffu, cA0, s);
            cA1 += __shfl_xor_sync(0xffffffffu, cA1, s);
            cA2 += __shfl_xor_sync(0xffffffffu, cA2, s);
            cA3 += __shfl_xor_sync(0xffffffffu, cA3, s);
            cB0 += __shfl_xor_sync(0xffffffffu, cB0, s);
            cB1 += __shfl_xor_sync(0xffffffffu, cB1, s);
            cB2 += __shfl_xor_sync(0xffffffffu, cB2, s);
            cB3 += __shfl_xor_sync(0xffffffffu, cB3, s);
        }

        // ---- PH^T rows for both batches (H quads shared)
        u64 a0 = 0ull, a1 = 0ull, b0 = 0ull, b1 = 0ull;
#pragma unroll
        for (int l = 0; l < Sn; ++l) {
            ulonglong2 h = *(const ulonglong2*)&sHTp[l * 2];
            u64 psA = pack2(pA[l], pA[l]);
            u64 psB = pack2(pB[l], pB[l]);
            a0 = ffma2(psA, h.x, a0); a1 = ffma2(psA, h.y, a1);
            b0 = ffma2(psB, h.x, b0); b1 = ffma2(psB, h.y, b1);
        }
        float phA0, phA1, phA2, phA3, phB0, phB1, phB2, phB3;
        unpack2(a0, phA0, phA1); unpack2(a1, phA2, phA3);
        unpack2(b0, phB0, phB1); unpack2(b1, phB2, phB3);
        phtA[0 * 34 + lane] = phA0; phtA[1 * 34 + lane] = phA1;
        phtA[2 * 34 + lane] = phA2; phtA[3 * 34 + lane] = phA3;
        phtB[0 * 34 + lane] = phB0; phtB[1 * 34 + lane] = phB1;
        phtB[2 * 34 + lane] = phB2; phtB[3 * 34 + lane] = phB3;

        if (lane == 0)
            *(float4*)&out_means[((size_t)t * Bn + bA) * 4] = make_float4(cA0, cA1, cA2, cA3);
        if (lane == 1)
            *(float4*)&out_means[((size_t)t * Bn + bB) * 4] = make_float4(cB0, cB1, cB2, cB3);
        float rA0 = yvA.x - cA0, rA1 = yvA.y - cA1, rA2 = yvA.z - cA2, rA3 = yvA.w - cA3;
        float rB0 = yvB.x - cB0, rB1 = yvB.y - cB1, rB2 = yvB.z - cB2, rB3 = yvB.w - cB3;
        __syncwarp();

        // ---- S entries: lanes 0-15 batch A, lanes 16-31 batch B
        int q = (lane >> 2) & 3, r = lane & 3;
        int sb = lane >> 4;
        float sv;
        {
            u64 acc2 = 0ull;
            const u64* hq = &sHR[q * 17];
            const u64* pr = &sPHT[sb][r * 17];
#pragma unroll
            for (int c = 0; c < 16; ++c)
                acc2 = ffma2(hq[c], pr[c], acc2);
            float alo, ahi; unpack2(acc2, alo, ahi);
            sv = sR16[(q << 2) | r] + (alo + ahi);
        }
        out_covs[((size_t)t * Bn + (bA + sb)) * 16 + ((q << 2) | r)] = sv;

        if (t == Tn - 1) break;

        // ---- broadcast S for both batches; dual rsqrt-Cholesky (interleaved)
        float sA00 = __shfl_sync(0xffffffffu, sv, 0);
        float sA10 = __shfl_sync(0xffffffffu, sv, 4);
        float sA11 = __shfl_sync(0xffffffffu, sv, 5);
        float sA20 = __shfl_sync(0xffffffffu, sv, 8);
        float sA21 = __shfl_sync(0xffffffffu, sv, 9);
        float sA22 = __shfl_sync(0xffffffffu, sv, 10);
        float sA30 = __shfl_sync(0xffffffffu, sv, 12);
        float sA31 = __shfl_sync(0xffffffffu, sv, 13);
        float sA32 = __shfl_sync(0xffffffffu, sv, 14);
        float sA33 = __shfl_sync(0xffffffffu, sv, 15);
        float sB00 = __shfl_sync(0xffffffffu, sv, 16);
        float sB10 = __shfl_sync(0xffffffffu, sv, 20);
        float sB11 = __shfl_sync(0xffffffffu, sv, 21);
        float sB20 = __shfl_sync(0xffffffffu, sv, 24);
        float sB21 = __shfl_sync(0xffffffffu, sv, 25);
        float sB22 = __shfl_sync(0xffffffffu, sv, 26);
        float sB30 = __shfl_sync(0xffffffffu, sv, 28);
        float sB31 = __shfl_sync(0xffffffffu, sv, 29);
        float sB32 = __shfl_sync(0xffffffffu, sv, 30);
        float sB33 = __shfl_sync(0xffffffffu, sv, 31);

        float iA0 = rsqrtf(sA00);
        float iB0 = rsqrtf(sB00);
        float LA10 = sA10 * iA0, LA20 = sA20 * iA0, LA30 = sA30 * iA0;
        float LB10 = sB10 * iB0, LB20 = sB20 * iB0, LB30 = sB30 * iB0;
        float iA1 = rsqrtf(sA11 - LA10 * LA10);
        float iB1 = rsqrtf(sB11 - LB10 * LB10);
        float LA21 = (sA21 - LA20 * LA10) * iA1;
        float LA31 = (sA31 - LA30 * LA10) * iA1;
        float LB21 = (sB21 - LB20 * LB10) * iB1;
        float LB31 = (sB31 - LB30 * LB10) * iB1;
        float iA2 = rsqrtf(sA22 - LA20 * LA20 - LA21 * LA21);
        float iB2 = rsqrtf(sB22 - LB20 * LB20 - LB21 * LB21);
        float LA32 = (sA32 - LA30 * LA20 - LA31 * LA21) * iA2;
        float LB32 = (sB32 - LB30 * LB20 - LB31 * LB21) * iB2;
        float iA3 = rsqrtf(sA33 - LA30 * LA30 - LA31 * LA31 - LA32 * LA32);
        float iB3 = rsqrtf(sB33 - LB30 * LB30 - LB31 * LB31 - LB32 * LB32);

        // ---- whitened z + gain rows (two independent chains)
        float zA0 = phA0 * iA0;
        float zB0 = phB0 * iB0;
        float zA1 = (phA1 - LA10 * zA0) * iA1;
        float zB1 = (phB1 - LB10 * zB0) * iB1;
        float zA2 = (phA2 - LA20 * zA0 - LA21 * zA1) * iA2;
        float zB2 = (phB2 - LB20 * zB0 - LB21 * zB1) * iB2;
        float zA3 = (phA3 - LA30 * zA0 - LA31 * zA1 - LA32 * zA2) * iA3;
        float zB3 = (phB3 - LB30 * zB0 - LB31 * zB1 - LB32 * zB2) * iB3;
        float kA3 = zA3 * iA3;
        float kB3 = zB3 * iB3;
        float kA2 = (zA2 - LA32 * kA3) * iA2;
        float kB2 = (zB2 - LB32 * kB3) * iB2;
        float kA1 = (zA1 - LA21 * kA2 - LA31 * kA3) * iA1;
        float kB1 = (zB1 - LB21 * kB2 - LB31 * kB3) * iB1;
        float kA0 = (zA0 - LA10 * kA1 - LA20 * kA2 - LA30 * kA3) * iA0;
        float kB0 = (zB0 - LB10 * kB1 - LB20 * kB2 - LB30 * kB3) * iB0;

        *(float4*)&sZ[0][lane * 4] = make_float4(zA0, zA1, zA2, zA3);
        *(float4*)&sZ[1][lane * 4] = make_float4(zB0, zB1, zB2, zB3);
        __syncwarp();

        // ---- mean updates
        mA = fmaf(kA0, rA0, fmaf(kA1, rA1, fmaf(kA2, rA2, fmaf(kA3, rA3, mA))));
        mB = fmaf(kB0, rB0, fmaf(kB1, rB1, fmaf(kB2, rB2, fmaf(kB3, rB3, mB))));
        muA[lane] = mA;
        muB[lane] = mB;

        // ---- symmetric rank-4 downdates (both batches, interleaved)
#pragma unroll
        for (int i = 0; i < Sn; ++i) {
            float4 za = *(const float4*)&sZ[0][i * 4];
            float4 zb = *(const float4*)&sZ[1][i * 4];
            float dA = za.x * zA0;
            float dB = zb.x * zB0;
            dA = fmaf(za.y, zA1, dA); dB = fmaf(zb.y, zB1, dB);
            dA = fmaf(za.z, zA2, dA); dB = fmaf(zb.z, zB2, dB);
            dA = fmaf(za.w, zA3, dA); dB = fmaf(zb.w, zB3, dB);
            pA[i] -= dA;
            pB[i] -= dB;
        }

        // ---- GEMM1 (two column-pass): X row `lane` = p . F^T, F reads shared
#pragma unroll
        for (int pass = 0; pass < 2; ++pass) {
            u64 xA[8], xB[8];
#pragma unroll
            for (int c = 0; c < 8; ++c) { xA[c] = 0ull; xB[c] = 0ull; }
#pragma unroll
            for (int l = 0; l < Sn; ++l) {
                const ulonglong2* fr = (const ulonglong2*)&sFTp[l * 18] + pass * 4;
                u64 psA = pack2(pA[l], pA[l]);
                u64 psB = pack2(pB[l], pB[l]);
#pragma unroll
                for (int c2 = 0; c2 < 4; ++c2) {
                    ulonglong2 f = fr[c2];
                    xA[2 * c2 + 0] = ffma2(psA, f.x, xA[2 * c2 + 0]);
                    xA[2 * c2 + 1] = ffma2(psA, f.y, xA[2 * c2 + 1]);
                    xB[2 * c2 + 0] = ffma2(psB, f.x, xB[2 * c2 + 0]);
                    xB[2 * c2 + 1] = ffma2(psB, f.y, xB[2 * c2 + 1]);
                }
            }
#pragma unroll
            for (int c = 0; c < 8; ++c) {
                *(u64*)&sX[0][lane * XLD + pass * 16 + 2 * c] = xA[c];
                *(u64*)&sX[1][lane * XLD + pass * 16 + 2 * c] = xB[c];
            }
        }
        __syncwarp();

        // ---- mean predict (F rows shared between batches)
        {
            u64 accA = 0ull, accB = 0ull;
            const u64* frw = &sFR[lane * 17];
#pragma unroll
            for (int c = 0; c < 16; ++c) {
                u64 f = frw[c];
                accA = ffma2(f, sMu[0][c], accA);
                accB = ffma2(f, sMu[1][c], accB);
            }
            float alo, ahi;
            unpack2(accA, alo, ahi); mA = alo + ahi;
            unpack2(accB, alo, ahi); mB = alo + ahi;
        }

        // ---- GEMM2 (single pass): P_new col `lane` = F*X[:,lane] + Q[:,lane]
        {
            u64 aAcc[16], bAcc[16];
            const ulonglong2* qr = (const ulonglong2*)&sQp[lane * 18];
#pragma unroll
            for (int c2 = 0; c2 < 8; ++c2) {
                ulonglong2 qq = qr[c2];
                aAcc[2 * c2 + 0] = qq.x; aAcc[2 * c2 + 1] = qq.y;
                bAcc[2 * c2 + 0] = qq.x; bAcc[2 * c2 + 1] = qq.y;
            }
#pragma unroll 4
            for (int k = 0; k < Sn; ++k) {
                float xvA = sX[0][k * XLD + lane];
                float xvB = sX[1][k * XLD + lane];
                u64 xsA = pack2(xvA, xvA);
                u64 xsB = pack2(xvB, xvB);
                const ulonglong2* fr = (const ulonglong2*)&sFTp[k * 18];
#pragma unroll
                for (int c2 = 0; c2 < 8; ++c2) {
                    ulonglong2 f = fr[c2];
                    aAcc[2 * c2 + 0] = ffma2(xsA, f.x, aAcc[2 * c2 + 0]);
                    aAcc[2 * c2 + 1] = ffma2(xsA, f.y, aAcc[2 * c2 + 1]);
                    bAcc[2 * c2 + 0] = ffma2(xsB, f.x, bAcc[2 * c2 + 0]);
                    bAcc[2 * c2 + 1] = ffma2(xsB, f.y, bAcc[2 * c2 + 1]);
                }
            }
#pragma unroll
            for (int c = 0; c < 16; ++c) {
                unpack2(aAcc[c], pA[2 * c], pA[2 * c + 1]);
                unpack2(bAcc[c], pB[2 * c], pB[2 * c + 1]);
            }
        }
        __syncwarp();
    }
}

extern "C" void kernel_launch(void* const* d_in, const int* in_sizes, int n_in,
                              void* d_out, int out_size)
{
    const float* obs       = (const float*)d_in[0];
    const float* Fm        = (const float*)d_in[1];
    const float* Qm        = (const float*)d_in[2];
    const float* Hm        = (const float*)d_in[3];
    const float* Rm        = (const float*)d_in[4];
    const float* init_mean = (const float*)d_in[5];
    const float* init_cov  = (const float*)d_in[6];
    float* out = (float*)d_out;

    kalman_kernel<<<Bn / 2, 32>>>(obs, Fm, Qm, Hm, Rm, init_mean, init_cov, out);
}

// round 7
// speedup vs baseline: 1.8300x; 1.8300x over previous
#include <cuda_runtime.h>
#include <math.h>

// Kalman filter one-step-ahead predictions. B=512, T=256, S=32, M=4.
// Warp-per-batch (32-thread blocks x 512), register-resident symmetric P
// (lane j holds column j == row j). Packed fma.rn.f32x2 GEMMs with
// uniform-broadcast LDS.128 of F. Serial chains split; mean-measurement via
// shared-memory dot (no butterfly); rsqrt Cholesky; stride-34 X buffer.

#define Bn 512
#define Tn 256
#define Sn 32
#define Mn 4
#define XLD 34  // sX row stride in floats: even (8B-aligned u64) + degree-2 banks

using u64 = unsigned long long;

__device__ __forceinline__ u64 pack2(float lo, float hi) {
    u64 r; asm("mov.b64 %0,{%1,%2};" : "=l"(r) : "f"(lo), "f"(hi)); return r;
}
__device__ __forceinline__ void unpack2(u64 v, float& lo, float& hi) {
    asm("mov.b64 {%0,%1},%2;" : "=f"(lo), "=f"(hi) : "l"(v));
}
__device__ __forceinline__ u64 ffma2(u64 a, u64 b, u64 c) {
    u64 d; asm("fma.rn.f32x2 %0,%1,%2,%3;" : "=l"(d) : "l"(a), "l"(b), "l"(c)); return d;
}
__device__ __forceinline__ u64 fadd2(u64 a, u64 b) {
    u64 d; asm("add.rn.f32x2 %0,%1,%2;" : "=l"(d) : "l"(a), "l"(b)); return d;
}

__global__ __launch_bounds__(32) void kalman_kernel(
    const float* __restrict__ obs,       // [B,T,M]
    const float* __restrict__ Fm,        // [S,S]
    const float* __restrict__ Qm,        // [S,S]
    const float* __restrict__ Hm,        // [M,S]
    const float* __restrict__ Rm,        // [M,M]
    const float* __restrict__ init_mean, // [B,S]
    const float* __restrict__ init_cov,  // [B,S,S]
    float* __restrict__ out)
{
    const int b    = blockIdx.x;
    const int lane = threadIdx.x;

    // F column pairs: float view fv[l*36+i] = F[i][l]
    __shared__ __align__(16) u64 sFTp[Sn * 18];
    // Q column pairs: float view [j*36+i] = Q[i][j]
    __shared__ __align__(16) u64 sQp[Sn * 18];
    // H per-l quads: float view [l*4+q] = H[q][l]  (PH GEMM)
    __shared__ __align__(16) u64 sHTp[Sn * 2];
    // H row-major pairs: float view hr[q*34+l] = H[q][l]  (S and mm dots)
    __shared__ __align__(16) u64 sHR[4 * 17];
    // F row-major pairs: float view fr[j*34+l] = F[j][l]  (mean predict)
    __shared__ __align__(16) u64 sFR[Sn * 17];
    // PH^T row-major: float view pht[r*34+l] = (P H^T)[l][r]
    __shared__ __align__(16) u64 sPHT[4 * 17];
    // X = P_u * F^T rows, stride 34
    __shared__ __align__(16) float sX[Sn * XLD];
    // whitened z per row
    __shared__ __align__(16) float sZ[Sn * 4];
    // updated mean pairs (for predict) and predicted mean pairs (for mm)
    __shared__ __align__(16) u64 sMu[16];
    __shared__ __align__(16) u64 sMp[16];
    __shared__ float sR16[16];

    {
        float* fv  = (float*)sFTp;
        float* qv  = (float*)sQp;
        float* frf = (float*)sFR;
        for (int idx = lane; idx < Sn * Sn; idx += 32) {
            int i = idx >> 5, l = idx & 31;
            float f = Fm[idx];
            fv [l * 36 + i] = f;
            frf[i * 34 + l] = f;
            qv [l * 36 + i] = Qm[idx];
        }
        float* hv  = (float*)sHTp;
        float* hrf = (float*)sHR;
        for (int idx = lane; idx < Mn * Sn; idx += 32) {
            int q = idx >> 5, l = idx & 31;
            float h = Hm[idx];
            hv [l * 4 + q]  = h;
            hrf[q * 34 + l] = h;
        }
        if (lane < 16) sR16[lane] = Rm[lane];
    }

    // per-lane state: P column `lane` (== row, symmetric), mean element
    float p[Sn];
#pragma unroll
    for (int i = 0; i < Sn; ++i)
        p[i] = init_cov[(size_t)b * (Sn * Sn) + i * Sn + lane];
    float mloc = init_mean[b * Sn + lane];

    float* muF  = (float*)sMu;
    float* mpF  = (float*)sMp;
    mpF[lane] = mloc;               // predicted mean for t=0 is the init mean
    __syncwarp();

    const float* yb = obs + (size_t)b * (Tn * Mn);
    float* out_means = out;                               // [T,B,M]
    float* out_covs  = out + (size_t)Tn * Bn * Mn;        // [T,B,M,M]

    float4 yn = *(const float4*)yb;  // prefetch y_0
    float* phtF = (float*)sPHT;

#pragma unroll 1
    for (int t = 0; t < Tn; ++t) {
        float4 yv = yn;
        int tnext = (t + 1 < Tn) ? (t + 1) : (Tn - 1);
        yn = *(const float4*)(yb + 4 * tnext);

        // ---- mm[q] on lane q (q<4): dot(H row q, m_p) via shared pairs
        float mmv = 0.f;
        {
            u64 accm0 = 0ull, accm1 = 0ull;
            const u64* hq = &sHR[(lane & 3) * 17];
#pragma unroll
            for (int c = 0; c < 8; ++c) {
                accm0 = ffma2(hq[2 * c + 0], sMp[2 * c + 0], accm0);
                accm1 = ffma2(hq[2 * c + 1], sMp[2 * c + 1], accm1);
            }
            u64 accm = fadd2(accm0, accm1);
            float alo, ahi; unpack2(accm, alo, ahi);
            mmv = alo + ahi;
        }

        // ---- phtt = row `lane` of P*H^T (packed, 4 split chains)
        u64 a00 = 0ull, a01 = 0ull, a10 = 0ull, a11 = 0ull;
#pragma unroll
        for (int l = 0; l < Sn; l += 2) {
            ulonglong2 h0 = *(const ulonglong2*)&sHTp[l * 2];
            ulonglong2 h1 = *(const ulonglong2*)&sHTp[(l + 1) * 2];
            u64 ps0 = pack2(p[l], p[l]);
            u64 ps1 = pack2(p[l + 1], p[l + 1]);
            a00 = ffma2(ps0, h0.x, a00); a10 = ffma2(ps0, h0.y, a10);
            a01 = ffma2(ps1, h1.x, a01); a11 = ffma2(ps1, h1.y, a11);
        }
        u64 ph2a = fadd2(a00, a01);
        u64 ph2b = fadd2(a10, a11);
        float ph0, ph1, phh2, ph3;
        unpack2(ph2a, ph0, ph1);
        unpack2(ph2b, phh2, ph3);
        phtF[0 * 34 + lane] = ph0;
        phtF[1 * 34 + lane] = ph1;
        phtF[2 * 34 + lane] = phh2;
        phtF[3 * 34 + lane] = ph3;

        // broadcast mm from lanes 0..3; residual everywhere
        float c0 = __shfl_sync(0xffffffffu, mmv, 0);
        float c1 = __shfl_sync(0xffffffffu, mmv, 1);
        float c2 = __shfl_sync(0xffffffffu, mmv, 2);
        float c3 = __shfl_sync(0xffffffffu, mmv, 3);
        if (lane == 0)
            *(float4*)&out_means[((size_t)t * Bn + b) * 4] = make_float4(c0, c1, c2, c3);
        float r0 = yv.x - c0, r1 = yv.y - c1, r2 = yv.z - c2, r3 = yv.w - c3;
        __syncwarp();

        // ---- S = H*(PH^T) + R : lane (q,r), duplicated for lanes>=16
        int q = (lane >> 2) & 3, r = lane & 3;
        float sv;
        {
            u64 acc0 = 0ull, acc1 = 0ull;
            const u64* hq = &sHR [q * 17];
            const u64* pr = &sPHT[r * 17];
#pragma unroll
            for (int c = 0; c < 8; ++c) {
                acc0 = ffma2(hq[2 * c + 0], pr[2 * c + 0], acc0);
                acc1 = ffma2(hq[2 * c + 1], pr[2 * c + 1], acc1);
            }
            u64 acc = fadd2(acc0, acc1);
            float alo, ahi; unpack2(acc, alo, ahi);
            sv = sR16[(q << 2) | r] + (alo + ahi);
        }
        if (lane < 16)
            out_covs[((size_t)t * Bn + b) * 16 + lane] = sv;  // mc_t == S_t

        if (t == Tn - 1) break;

        // ---- broadcast S, redundant rsqrt-form 4x4 Cholesky in every lane
        float s00 = __shfl_sync(0xffffffffu, sv, 0);
        float s10 = __shfl_sync(0xffffffffu, sv, 4);
        float s11 = __shfl_sync(0xffffffffu, sv, 5);
        float s20 = __shfl_sync(0xffffffffu, sv, 8);
        float s21 = __shfl_sync(0xffffffffu, sv, 9);
        float s22 = __shfl_sync(0xffffffffu, sv, 10);
        float s30 = __shfl_sync(0xffffffffu, sv, 12);
        float s31 = __shfl_sync(0xffffffffu, sv, 13);
        float s32 = __shfl_sync(0xffffffffu, sv, 14);
        float s33 = __shfl_sync(0xffffffffu, sv, 15);
        float i0 = rsqrtf(s00);
        float L10 = s10 * i0, L20 = s20 * i0, L30 = s30 * i0;
        float i1 = rsqrtf(s11 - L10 * L10);
        float L21 = (s21 - L20 * L10) * i1;
        float L31 = (s31 - L30 * L10) * i1;
        float i2 = rsqrtf(s22 - L20 * L20 - L21 * L21);
        float L32 = (s32 - L30 * L20 - L31 * L21) * i2;
        float i3 = rsqrtf(s33 - L30 * L30 - L31 * L31 - L32 * L32);

        // ---- whitened z (forward) and gain row (back solve), per lane
        float z0 = ph0 * i0;
        float z1 = (ph1 - L10 * z0) * i1;
        float z2 = (phh2 - L20 * z0 - L21 * z1) * i2;
        float z3 = (ph3 - L30 * z0 - L31 * z1 - L32 * z2) * i3;
        float k3 = z3 * i3;
        float k2 = (z2 - L32 * k3) * i2;
        float k1 = (z1 - L21 * k2 - L31 * k3) * i1;
        float k0 = (z0 - L10 * k1 - L20 * k2 - L30 * k3) * i0;

        *(float4*)&sZ[lane * 4] = make_float4(z0, z1, z2, z3);
        __syncwarp();

        // ---- mean update + publish m_u pairs
        mloc = fmaf(k0, r0, fmaf(k1, r1, fmaf(k2, r2, fmaf(k3, r3, mloc))));
        muF[lane] = mloc;

        // ---- covariance downdate: p[i] -= z_i . z_lane (bitwise symmetric)
#pragma unroll
        for (int i = 0; i < Sn; ++i) {
            float4 zi = *(const float4*)&sZ[i * 4];
            float d = zi.x * z0;
            d = fmaf(zi.y, z1, d);
            d = fmaf(zi.z, z2, d);
            d = fmaf(zi.w, z3, d);
            p[i] -= d;
        }

        // ---- GEMM1: X row `lane` = p . F^T
        u64 x2[16];
#pragma unroll
        for (int c = 0; c < 16; ++c) x2[c] = 0ull;
#pragma unroll
        for (int l = 0; l < Sn; ++l) {
            u64 ps = pack2(p[l], p[l]);
            const ulonglong2* fr = (const ulonglong2*)&sFTp[l * 18];
#pragma unroll
            for (int c2 = 0; c2 < 8; ++c2) {
                ulonglong2 f = fr[c2];
                x2[2 * c2 + 0] = ffma2(ps, f.x, x2[2 * c2 + 0]);
                x2[2 * c2 + 1] = ffma2(ps, f.y, x2[2 * c2 + 1]);
            }
        }
#pragma unroll
        for (int c = 0; c < 16; ++c)
            *(u64*)&sX[lane * XLD + 2 * c] = x2[c];
        __syncwarp();

        // ---- mean predict: mp[lane] = sum_l F[lane][l]*m_u[l] (2 split chains)
        float mp;
        {
            u64 acc0 = 0ull, acc1 = 0ull;
            const u64* frw = &sFR[lane * 17];
#pragma unroll
            for (int c = 0; c < 8; ++c) {
                acc0 = ffma2(frw[2 * c + 0], sMu[2 * c + 0], acc0);
                acc1 = ffma2(frw[2 * c + 1], sMu[2 * c + 1], acc1);
            }
            u64 acc = fadd2(acc0, acc1);
            float alo, ahi; unpack2(acc, alo, ahi);
            mp = alo + ahi;
        }

        // ---- GEMM2: P_new column `lane` = F * X[:,lane] + Q[:,lane]
        u64 a2[16];
        {
            const ulonglong2* qr = (const ulonglong2*)&sQp[lane * 18];
#pragma unroll
            for (int c2 = 0; c2 < 8; ++c2) {
                ulonglong2 qq = qr[c2];
                a2[2 * c2 + 0] = qq.x;
                a2[2 * c2 + 1] = qq.y;
            }
        }
#pragma unroll 8
        for (int k = 0; k < Sn; ++k) {
            float xv = sX[k * XLD + lane];
            u64 xs = pack2(xv, xv);
            const ulonglong2* fr = (const ulonglong2*)&sFTp[k * 18];
#pragma unroll
            for (int c2 = 0; c2 < 8; ++c2) {
                ulonglong2 f = fr[c2];
                a2[2 * c2 + 0] = ffma2(xs, f.x, a2[2 * c2 + 0]);
                a2[2 * c2 + 1] = ffma2(xs, f.y, a2[2 * c2 + 1]);
            }
        }
#pragma unroll
        for (int c = 0; c < 16; ++c)
            unpack2(a2[c], p[2 * c], p[2 * c + 1]);

        mloc = mp;
        mpF[lane] = mp;     // predicted mean pairs for next step's mm dot
        __syncwarp();
    }
}

extern "C" void kernel_launch(void* const* d_in, const int* in_sizes, int n_in,
                              void* d_out, int out_size)
{
    const float* obs       = (const float*)d_in[0];
    const float* Fm        = (const float*)d_in[1];
    const float* Qm        = (const float*)d_in[2];
    const float* Hm        = (const float*)d_in[3];
    const float* Rm        = (const float*)d_in[4];
    const float* init_mean = (const float*)d_in[5];
    const float* init_cov  = (const float*)d_in[6];
    float* out = (float*)d_out;

    kalman_kernel<<<Bn, 32>>>(obs, Fm, Qm, Hm, Rm, init_mean, init_cov, out);
}